// round 11
// baseline (speedup 1.0000x reference)
#include <cuda_runtime.h>

// Problem constants
#define NB   32
#define NCH  3
#define HH   128
#define RR   127      // output spatial size = H - K + 1
#define NLOC (NB*RR*RR)
#define TPB  128

// ---------------------------------------------------------------------------
// f32x2 packed-math helpers (sm_103a: 2 fp32 FLOPs per fma-pipe slot)
// ---------------------------------------------------------------------------
typedef unsigned long long f32x2_t;

__device__ __forceinline__ f32x2_t pk2(float lo, float hi) {
    f32x2_t r; asm("mov.b64 %0, {%1, %2};" : "=l"(r) : "f"(lo), "f"(hi)); return r;
}
__device__ __forceinline__ void upk2(f32x2_t v, float& lo, float& hi) {
    asm("mov.b64 {%0, %1}, %2;" : "=f"(lo), "=f"(hi) : "l"(v));
}
__device__ __forceinline__ f32x2_t mul2(f32x2_t a, f32x2_t b) {
    f32x2_t r; asm("mul.rn.f32x2 %0, %1, %2;" : "=l"(r) : "l"(a), "l"(b)); return r;
}
__device__ __forceinline__ f32x2_t fma2(f32x2_t a, f32x2_t b, f32x2_t c) {
    f32x2_t r; asm("fma.rn.f32x2 %0, %1, %2, %3;" : "=l"(r) : "l"(a), "l"(b), "l"(c)); return r;
}

// ---------------------------------------------------------------------------
// Single fused kernel (R10 skeleton). Threads 0-15 build U in shared memory
// (__sincosf only: register-cheap prep) in TWO forms:
//   sU  [256] plain floats          (scalar rows for channel 2)
//   sU2 [256] duplicated {u,u} pairs (packed rows for channels 0/1)
// Each thread computes ONE output location:
//   channels 0/1 packed in f32x2 lanes, channel 2 scalar.
//   Row 0 skipped: U orthogonal & |s_c|=1 => sum_r P_r = NCH exactly, so
//   z_q = 3 - 2 * (sum of P_r over rows with bit(3-q) set).
// ---------------------------------------------------------------------------
__global__ void rqcnn_main(const float* __restrict__ x,
                           const float* __restrict__ w,
                           float* __restrict__ out) {
    __shared__ __align__(16) f32x2_t sU2[256];
    __shared__ __align__(16) float   sU[256];

    if (threadIdx.x < 16) {
        int jj = threadIdx.x;
        float m[16];
#pragma unroll
        for (int i = 0; i < 16; i++) m[i] = (i == jj) ? 1.0f : 0.0f;
        for (int layer = 0; layer < 4; layer++) {
#pragma unroll
            for (int q = 0; q < 4; q++) {
                float t = 0.5f * w[layer * 4 + q];
                float c, s;
                __sincosf(t, &s, &c);          // |t| <= pi: MUFU fast path
                int mask = 8 >> q;
#pragma unroll
                for (int i0 = 0; i0 < 16; i0++) {
                    if (i0 & mask) continue;
                    int i1 = i0 | mask;
                    float a0 = m[i0], a1 = m[i1];
                    m[i0] = c * a0 - s * a1;
                    m[i1] = s * a0 + c * a1;
                }
            }
#pragma unroll
            for (int i = 0; i < 16; i++)
                if ((i & 8) && !(i & 4)) { float tt = m[i]; m[i] = m[i | 4]; m[i | 4] = tt; }
#pragma unroll
            for (int i = 0; i < 16; i++)
                if ((i & 2) && !(i & 1)) { float tt = m[i]; m[i] = m[i | 1]; m[i | 1] = tt; }
#pragma unroll
            for (int i = 0; i < 16; i++)
                if ((i & 4) && !(i & 2)) { float tt = m[i]; m[i] = m[i | 2]; m[i | 2] = tt; }
        }
#pragma unroll
        for (int i = 0; i < 16; i++) {
            sU[i * 16 + jj]  = m[i];
            sU2[i * 16 + jj] = pk2(m[i], m[i]);
        }
    }
    __syncthreads();

    int gid = blockIdx.x * TPB + threadIdx.x;
    if (gid >= NLOC) return;

    int j  = gid % RR;
    int t2 = gid / RR;
    int i  = t2 % RR;
    int b  = t2 / RR;

    const float HPI = 1.57079632679489662f;  // pi/2

    // ---- channels 0 and 1: packed product state s01[16] (lanes = ch0, ch1)
    f32x2_t s01[16];
    {
        const float* px0 = x + (((b * NCH + 0) * HH) + i) * HH + j;
        const float* px1 = px0 + HH * HH;
        float a0c, a0s, b0c, b0s, c0c, c0s, d0c, d0s;
        float a1c, a1s, b1c, b1s, c1c, c1s, d1c, d1s;
        __sincosf(px0[0]      * HPI, &a0s, &a0c);
        __sincosf(px0[1]      * HPI, &b0s, &b0c);
        __sincosf(px0[HH]     * HPI, &c0s, &c0c);
        __sincosf(px0[HH + 1] * HPI, &d0s, &d0c);
        __sincosf(px1[0]      * HPI, &a1s, &a1c);
        __sincosf(px1[1]      * HPI, &b1s, &b1c);
        __sincosf(px1[HH]     * HPI, &c1s, &c1c);
        __sincosf(px1[HH + 1] * HPI, &d1s, &d1c);

        f32x2_t ca = pk2(a0c, a1c), sa = pk2(a0s, a1s);
        f32x2_t cb = pk2(b0c, b1c), sb = pk2(b0s, b1s);
        f32x2_t cc = pk2(c0c, c1c), sc = pk2(c0s, c1s);
        f32x2_t cd = pk2(d0c, d1c), sd = pk2(d0s, d1s);

        f32x2_t ab00 = mul2(ca, cb), ab01 = mul2(ca, sb);
        f32x2_t ab10 = mul2(sa, cb), ab11 = mul2(sa, sb);
        f32x2_t cd00 = mul2(cc, cd), cd01 = mul2(cc, sd);
        f32x2_t cd10 = mul2(sc, cd), cd11 = mul2(sc, sd);

        s01[0]  = mul2(ab00, cd00); s01[1]  = mul2(ab00, cd01); s01[2]  = mul2(ab00, cd10); s01[3]  = mul2(ab00, cd11);
        s01[4]  = mul2(ab01, cd00); s01[5]  = mul2(ab01, cd01); s01[6]  = mul2(ab01, cd10); s01[7]  = mul2(ab01, cd11);
        s01[8]  = mul2(ab10, cd00); s01[9]  = mul2(ab10, cd01); s01[10] = mul2(ab10, cd10); s01[11] = mul2(ab10, cd11);
        s01[12] = mul2(ab11, cd00); s01[13] = mul2(ab11, cd01); s01[14] = mul2(ab11, cd10); s01[15] = mul2(ab11, cd11);
    }

    // ---- channel 2: scalar product state s2[16]
    float s2[16];
    {
        const float* px = x + (((b * NCH + 2) * HH) + i) * HH + j;
        float ca, sa, cb, sb, cc, sc, cd, sd;
        __sincosf(px[0]      * HPI, &sa, &ca);
        __sincosf(px[1]      * HPI, &sb, &cb);
        __sincosf(px[HH]     * HPI, &sc, &cc);
        __sincosf(px[HH + 1] * HPI, &sd, &cd);
        float ab00 = ca * cb, ab01 = ca * sb, ab10 = sa * cb, ab11 = sa * sb;
        float cd00 = cc * cd, cd01 = cc * sd, cd10 = sc * cd, cd11 = sc * sd;
        s2[0]  = ab00 * cd00; s2[1]  = ab00 * cd01; s2[2]  = ab00 * cd10; s2[3]  = ab00 * cd11;
        s2[4]  = ab01 * cd00; s2[5]  = ab01 * cd01; s2[6]  = ab01 * cd10; s2[7]  = ab01 * cd11;
        s2[8]  = ab10 * cd00; s2[9]  = ab10 * cd01; s2[10] = ab10 * cd10; s2[11] = ab10 * cd11;
        s2[12] = ab11 * cd00; s2[13] = ab11 * cd01; s2[14] = ab11 * cd10; s2[15] = ab11 * cd11;
    }

    // ---- rows 1..15: P[r] = y0^2 + y1^2 + y2^2 (row 0 skipped via orthogonality)
    float P[16];
#pragma unroll
    for (int r = 1; r < 16; r++) {
        const ulonglong2* row2 = reinterpret_cast<const ulonglong2*>(sU2 + r * 16);
        const float4*     rowf = reinterpret_cast<const float4*>(sU + r * 16);
        ulonglong2 q0 = row2[0], q1 = row2[1], q2 = row2[2], q3 = row2[3];
        f32x2_t y01;
        y01 = mul2(q0.x, s01[0]);
        y01 = fma2(q0.y, s01[1],  y01);
        y01 = fma2(q1.x, s01[2],  y01);
        y01 = fma2(q1.y, s01[3],  y01);
        y01 = fma2(q2.x, s01[4],  y01);
        y01 = fma2(q2.y, s01[5],  y01);
        y01 = fma2(q3.x, s01[6],  y01);
        y01 = fma2(q3.y, s01[7],  y01);
        ulonglong2 q4 = row2[4], q5 = row2[5], q6 = row2[6], q7 = row2[7];
        y01 = fma2(q4.x, s01[8],  y01);
        y01 = fma2(q4.y, s01[9],  y01);
        y01 = fma2(q5.x, s01[10], y01);
        y01 = fma2(q5.y, s01[11], y01);
        y01 = fma2(q6.x, s01[12], y01);
        y01 = fma2(q6.y, s01[13], y01);
        y01 = fma2(q7.x, s01[14], y01);
        y01 = fma2(q7.y, s01[15], y01);

        float4 u0 = rowf[0], u1 = rowf[1], u2 = rowf[2], u3 = rowf[3];
        float y2v;
        y2v = u0.x * s2[0];
        y2v = fmaf(u0.y, s2[1],  y2v);
        y2v = fmaf(u0.z, s2[2],  y2v);
        y2v = fmaf(u0.w, s2[3],  y2v);
        y2v = fmaf(u1.x, s2[4],  y2v);
        y2v = fmaf(u1.y, s2[5],  y2v);
        y2v = fmaf(u1.z, s2[6],  y2v);
        y2v = fmaf(u1.w, s2[7],  y2v);
        y2v = fmaf(u2.x, s2[8],  y2v);
        y2v = fmaf(u2.y, s2[9],  y2v);
        y2v = fmaf(u2.z, s2[10], y2v);
        y2v = fmaf(u2.w, s2[11], y2v);
        y2v = fmaf(u3.x, s2[12], y2v);
        y2v = fmaf(u3.y, s2[13], y2v);
        y2v = fmaf(u3.z, s2[14], y2v);
        y2v = fmaf(u3.w, s2[15], y2v);

        f32x2_t p01 = mul2(y01, y01);
        float plo, phi;
        upk2(p01, plo, phi);
        P[r] = fmaf(y2v, y2v, plo + phi);
    }

    // ---- z_q = 3 - 2 * S_q,  S_q = sum of P_r over rows with bit(3-q) set
    float t23   = P[2]  + P[3],  t45   = P[4]  + P[5];
    float t67   = P[6]  + P[7],  t89   = P[8]  + P[9];
    float t1011 = P[10] + P[11], t1213 = P[12] + P[13];
    float t1415 = P[14] + P[15];
    float A = t89 + t1011, B = t1213 + t1415, C = t45 + t67;
    float S0 = A + B;                              // bit3 set: 8..15
    float S1 = C + B;                              // bit2 set: 4-7, 12-15
    float S2 = (t23 + t67) + (t1011 + t1415);      // bit1 set: 2,3,6,7,10,11,14,15
    float S3 = ((P[1] + P[3]) + (P[5] + P[7]))     // bit0 set: odd rows
             + ((P[9] + P[11]) + (P[13] + P[15]));
    float z0 = fmaf(-2.0f, S0, 3.0f);
    float z1 = fmaf(-2.0f, S1, 3.0f);
    float z2 = fmaf(-2.0f, S2, 3.0f);
    float z3 = fmaf(-2.0f, S3, 3.0f);

    // Output: q_out[B,R,R,DEPTH] contiguous (memory reinterpret of [B,DEPTH,R,R])
    reinterpret_cast<float4*>(out)[gid] = make_float4(z0, z1, z2, z3);
}

extern "C" void kernel_launch(void* const* d_in, const int* in_sizes, int n_in,
                              void* d_out, int out_size) {
    const float* x = (const float*)d_in[0];   // [32,3,128,128] float32
    const float* w = (const float*)d_in[1];   // [4,4] float32
    float* out = (float*)d_out;               // [32,4,127,127] float32

    int blocks = (NLOC + TPB - 1) / TPB;
    rqcnn_main<<<blocks, TPB>>>(x, w, out);
}

// round 12
// speedup vs baseline: 1.2260x; 1.2260x over previous
#include <cuda_runtime.h>

// Problem constants
#define NB   32
#define NCH  3
#define HH   128
#define RR   127      // output spatial size = H - K + 1
#define NLOC (NB*RR*RR)
#define TPB  128

// ---------------------------------------------------------------------------
// Single fused kernel — R10's allocation-clean scalar shape (86 regs, no
// spill, FFMA pipe saturated) with two pure-FLOP cuts:
//  * Row 0 of U skipped: U orthogonal & |s_c|=1  =>  sum_r P_r = 3 exactly,
//    so z_q = 3 - 2*S_q where S_q sums P_r over rows with bit(3-q) set.
//  * Cheaper S_q tree instead of the full signed butterfly.
// Threads 0-15 build U in shared via __sincosf (register-cheap prep path).
// ---------------------------------------------------------------------------
__global__ void rqcnn_main(const float* __restrict__ x,
                           const float* __restrict__ w,
                           float* __restrict__ out) {
    __shared__ __align__(16) float sU[256];

    if (threadIdx.x < 16) {
        int jj = threadIdx.x;
        float m[16];
#pragma unroll
        for (int i = 0; i < 16; i++) m[i] = (i == jj) ? 1.0f : 0.0f;
        for (int layer = 0; layer < 4; layer++) {
#pragma unroll
            for (int q = 0; q < 4; q++) {
                float t = 0.5f * w[layer * 4 + q];
                float c, s;
                __sincosf(t, &s, &c);          // |t| <= pi: MUFU fast path only
                int mask = 8 >> q;
#pragma unroll
                for (int i0 = 0; i0 < 16; i0++) {
                    if (i0 & mask) continue;
                    int i1 = i0 | mask;
                    float a0 = m[i0], a1 = m[i1];
                    m[i0] = c * a0 - s * a1;
                    m[i1] = s * a0 + c * a1;
                }
            }
            // CNOT(0,1): ctrl bit 8, tgt bit 4
#pragma unroll
            for (int i = 0; i < 16; i++)
                if ((i & 8) && !(i & 4)) { float tt = m[i]; m[i] = m[i | 4]; m[i | 4] = tt; }
            // CNOT(2,3): ctrl bit 2, tgt bit 1
#pragma unroll
            for (int i = 0; i < 16; i++)
                if ((i & 2) && !(i & 1)) { float tt = m[i]; m[i] = m[i | 1]; m[i | 1] = tt; }
            // CNOT(1,2): ctrl bit 4, tgt bit 2
#pragma unroll
            for (int i = 0; i < 16; i++)
                if ((i & 4) && !(i & 2)) { float tt = m[i]; m[i] = m[i | 2]; m[i | 2] = tt; }
        }
#pragma unroll
        for (int i = 0; i < 16; i++) sU[i * 16 + jj] = m[i];
    }
    __syncthreads();

    int gid = blockIdx.x * TPB + threadIdx.x;
    if (gid >= NLOC) return;

    int j  = gid % RR;
    int t2 = gid / RR;
    int i  = t2 % RR;
    int b  = t2 / RR;

    const float HPI = 1.57079632679489662f;  // pi/2

    float s[NCH][16];
#pragma unroll
    for (int c = 0; c < NCH; c++) {
        const float* px = x + (((b * NCH + c) * HH) + i) * HH + j;
        float p00 = px[0], p01 = px[1], p10 = px[HH], p11 = px[HH + 1];
        float ca, sa, cb, sb, cc, sc, cd, sd;
        __sincosf(p00 * HPI, &sa, &ca);   // qubit a: (i,   j)
        __sincosf(p01 * HPI, &sb, &cb);   // qubit b: (i,   j+1)
        __sincosf(p10 * HPI, &sc, &cc);   // qubit c: (i+1, j)
        __sincosf(p11 * HPI, &sd, &cd);   // qubit d: (i+1, j+1)

        float ab00 = ca * cb, ab01 = ca * sb, ab10 = sa * cb, ab11 = sa * sb;
        float cd00 = cc * cd, cd01 = cc * sd, cd10 = sc * cd, cd11 = sc * sd;

        s[c][0]  = ab00 * cd00; s[c][1]  = ab00 * cd01; s[c][2]  = ab00 * cd10; s[c][3]  = ab00 * cd11;
        s[c][4]  = ab01 * cd00; s[c][5]  = ab01 * cd01; s[c][6]  = ab01 * cd10; s[c][7]  = ab01 * cd11;
        s[c][8]  = ab10 * cd00; s[c][9]  = ab10 * cd01; s[c][10] = ab10 * cd10; s[c][11] = ab10 * cd11;
        s[c][12] = ab11 * cd00; s[c][13] = ab11 * cd01; s[c][14] = ab11 * cd10; s[c][15] = ab11 * cd11;
    }

    // Rows 1..15 only (row 0 recovered from sum P = 3)
    float P[16];
#pragma unroll
    for (int r = 1; r < 16; r++) {
        const float4* row = reinterpret_cast<const float4*>(sU + r * 16);
        float4 u0 = row[0], u1 = row[1], u2 = row[2], u3 = row[3];
        float acc = 0.0f;
#pragma unroll
        for (int c = 0; c < NCH; c++) {
            float y;
            y = u0.x * s[c][0];
            y = fmaf(u0.y, s[c][1],  y);
            y = fmaf(u0.z, s[c][2],  y);
            y = fmaf(u0.w, s[c][3],  y);
            y = fmaf(u1.x, s[c][4],  y);
            y = fmaf(u1.y, s[c][5],  y);
            y = fmaf(u1.z, s[c][6],  y);
            y = fmaf(u1.w, s[c][7],  y);
            y = fmaf(u2.x, s[c][8],  y);
            y = fmaf(u2.y, s[c][9],  y);
            y = fmaf(u2.z, s[c][10], y);
            y = fmaf(u2.w, s[c][11], y);
            y = fmaf(u3.x, s[c][12], y);
            y = fmaf(u3.y, s[c][13], y);
            y = fmaf(u3.z, s[c][14], y);
            y = fmaf(u3.w, s[c][15], y);
            acc = fmaf(y, y, acc);
        }
        P[r] = acc;
    }

    // z_q = 3 - 2*S_q,  S_q = sum of P_r over rows with bit(3-q) set
    float t23   = P[2]  + P[3],  t45   = P[4]  + P[5];
    float t67   = P[6]  + P[7],  t89   = P[8]  + P[9];
    float t1011 = P[10] + P[11], t1213 = P[12] + P[13];
    float t1415 = P[14] + P[15];
    float A = t89 + t1011, B = t1213 + t1415, C = t45 + t67;
    float S0 = A + B;                              // bit3 set: rows 8..15
    float S1 = C + B;                              // bit2 set: rows 4-7, 12-15
    float S2 = (t23 + t67) + (t1011 + t1415);      // bit1 set: 2,3,6,7,10,11,14,15
    float S3 = ((P[1] + P[3]) + (P[5] + P[7]))     // bit0 set: odd rows
             + ((P[9] + P[11]) + (P[13] + P[15]));
    float z0 = fmaf(-2.0f, S0, 3.0f);
    float z1 = fmaf(-2.0f, S1, 3.0f);
    float z2 = fmaf(-2.0f, S2, 3.0f);
    float z3 = fmaf(-2.0f, S3, 3.0f);

    // Output: q_out[B,R,R,DEPTH] contiguous (memory reinterpret of [B,DEPTH,R,R])
    reinterpret_cast<float4*>(out)[gid] = make_float4(z0, z1, z2, z3);
}

extern "C" void kernel_launch(void* const* d_in, const int* in_sizes, int n_in,
                              void* d_out, int out_size) {
    const float* x = (const float*)d_in[0];   // [32,3,128,128] float32
    const float* w = (const float*)d_in[1];   // [4,4] float32
    float* out = (float*)d_out;               // [32,4,127,127] float32

    int blocks = (NLOC + TPB - 1) / TPB;
    rqcnn_main<<<blocks, TPB>>>(x, w, out);
}

// round 14
// speedup vs baseline: 1.4382x; 1.1731x over previous
#include <cuda_runtime.h>
#include <cstdint>

#define NB   32
#define NCH  3
#define HH   128
#define RR   127
#define NLOC (NB*RR*RR)
#define TPB  128
#define ROWB 48            // staging row pitch (conflict-free: 3r mod 8 distinct)

struct SmemT {
    float U[256];                                   // circuit matrix, f32
    __align__(16) unsigned char stage[4][2][32 * ROWB];  // [warp][hi/lo][row]
};

__device__ __forceinline__ uint32_t smem_u32(const void* p) {
    uint32_t a;
    asm("{ .reg .u64 t; cvta.to.shared.u64 t, %1; cvt.u32.u64 %0, t; }" : "=r"(a) : "l"(p));
    return a;
}
// pack two f32 into bf16x2 by truncation (hi parts): low half = a, high = b
__device__ __forceinline__ uint32_t pk_hi(float a, float b) {
    return (__float_as_uint(b) & 0xFFFF0000u) | (__float_as_uint(a) >> 16);
}
__device__ __forceinline__ float hi_f32(float a) {
    return __uint_as_float(__float_as_uint(a) & 0xFFFF0000u);
}
// round-to-nearest pack: low half = a, high = b
__device__ __forceinline__ uint32_t pk_rn(float a, float b) {
    uint32_t d;
    asm("cvt.rn.bf16x2.f32 %0, %1, %2;" : "=r"(d) : "f"(b), "f"(a));
    return d;
}
__device__ __forceinline__ void ldsm4(uint32_t& r0, uint32_t& r1, uint32_t& r2, uint32_t& r3,
                                      uint32_t addr) {
    asm volatile("ldmatrix.sync.aligned.m8n8.x4.shared.b16 {%0,%1,%2,%3}, [%4];"
                 : "=r"(r0), "=r"(r1), "=r"(r2), "=r"(r3) : "r"(addr));
}
__device__ __forceinline__ void mma16816(float& d0, float& d1, float& d2, float& d3,
                                         uint32_t a0, uint32_t a1, uint32_t a2, uint32_t a3,
                                         uint32_t b0, uint32_t b1) {
    asm volatile("mma.sync.aligned.m16n8k16.row.col.f32.bf16.bf16.f32 "
                 "{%0,%1,%2,%3}, {%4,%5,%6,%7}, {%8,%9}, {%0,%1,%2,%3};"
                 : "+f"(d0), "+f"(d1), "+f"(d2), "+f"(d3)
                 : "r"(a0), "r"(a1), "r"(a2), "r"(a3), "r"(b0), "r"(b1));
}

__global__ void rqcnn_mma(const float* __restrict__ x,
                          const float* __restrict__ w,
                          float* __restrict__ out) {
    __shared__ SmemT sm;
    int tid  = threadIdx.x;
    int wid  = tid >> 5;
    int lane = tid & 31;

    // ---- build U (threads 0-15, column each), __sincosf = register-cheap ----
    if (tid < 16) {
        int jj = tid;
        float m[16];
#pragma unroll
        for (int i = 0; i < 16; i++) m[i] = (i == jj) ? 1.0f : 0.0f;
        for (int layer = 0; layer < 4; layer++) {
#pragma unroll
            for (int q = 0; q < 4; q++) {
                float t = 0.5f * w[layer * 4 + q];
                float c, s;
                __sincosf(t, &s, &c);
                int mask = 8 >> q;
#pragma unroll
                for (int i0 = 0; i0 < 16; i0++) {
                    if (i0 & mask) continue;
                    int i1 = i0 | mask;
                    float a0 = m[i0], a1 = m[i1];
                    m[i0] = c * a0 - s * a1;
                    m[i1] = s * a0 + c * a1;
                }
            }
#pragma unroll
            for (int i = 0; i < 16; i++)
                if ((i & 8) && !(i & 4)) { float tt = m[i]; m[i] = m[i | 4]; m[i | 4] = tt; }
#pragma unroll
            for (int i = 0; i < 16; i++)
                if ((i & 2) && !(i & 1)) { float tt = m[i]; m[i] = m[i | 1]; m[i | 1] = tt; }
#pragma unroll
            for (int i = 0; i < 16; i++)
                if ((i & 4) && !(i & 2)) { float tt = m[i]; m[i] = m[i | 2]; m[i | 2] = tt; }
        }
#pragma unroll
        for (int i = 0; i < 16; i++) sm.U[i * 16 + jj] = m[i];
    }
    __syncthreads();

    int t = lane & 3, g = lane >> 2;

    // ---- B fragments (built once): B[k][n] = U[n][k], n = g + 8*nt ----
    // b0 = {U[n][2t], U[n][2t+1]}, b1 = {U[n][2t+8], U[n][2t+9]} (low half first)
    uint32_t bh0[2], bh1[2], bl0[2], bl1[2];
#pragma unroll
    for (int nt = 0; nt < 2; nt++) {
        const float* Ur = sm.U + (g + 8 * nt) * 16;
        float u0 = Ur[2 * t],     u1 = Ur[2 * t + 1];
        float u2 = Ur[2 * t + 8], u3 = Ur[2 * t + 9];
        bh0[nt] = pk_hi(u0, u1);
        bh1[nt] = pk_hi(u2, u3);
        bl0[nt] = pk_rn(u0 - hi_f32(u0), u1 - hi_f32(u1));
        bl1[nt] = pk_rn(u2 - hi_f32(u2), u3 - hi_f32(u3));
    }

    // ---- per-lane patch ----
    int gid = blockIdx.x * TPB + tid;
    int gcl = (gid < NLOC) ? gid : (NLOC - 1);
    int j   = gcl % RR;
    int t2  = gcl / RR;
    int i   = t2 % RR;
    int b   = t2 / RR;
    const float HPI = 1.57079632679489662f;

    uint32_t hibase = smem_u32(&sm.stage[wid][0][0]);
    uint32_t lobase = smem_u32(&sm.stage[wid][1][0]);
    uint4* hrow = reinterpret_cast<uint4*>(&sm.stage[wid][0][lane * ROWB]);
    uint4* lrow = reinterpret_cast<uint4*>(&sm.stage[wid][1][lane * ROWB]);
    uint32_t lmoff = (uint32_t)((lane & 15) * ROWB + (lane & 16));

    float P[2][2][4];
#pragma unroll
    for (int a = 0; a < 2; a++)
#pragma unroll
        for (int n = 0; n < 2; n++)
#pragma unroll
            for (int e = 0; e < 4; e++) P[a][n][e] = 0.0f;

    const float* px = x + (((b * NCH) * HH) + i) * HH + j;

#pragma unroll 1
    for (int c = 0; c < NCH; c++) {
        __syncwarp();   // prior ldmatrix done before staging overwrite

        // scalar 4B loads (odd-j bases are only 4B aligned)
        float p00 = px[0], p01 = px[1], p10 = px[HH], p11 = px[HH + 1];
        px += HH * HH;

        float ca, sa, cb, sb, cc, sc, cd, sd;
        __sincosf(p00 * HPI, &sa, &ca);
        __sincosf(p01 * HPI, &sb, &cb);
        __sincosf(p10 * HPI, &sc, &cc);
        __sincosf(p11 * HPI, &sd, &cd);
        float ab00 = ca * cb, ab01 = ca * sb, ab10 = sa * cb, ab11 = sa * sb;
        float cd00 = cc * cd, cd01 = cc * sd, cd10 = sc * cd, cd11 = sc * sd;
        float s[16];
        s[0]  = ab00 * cd00; s[1]  = ab00 * cd01; s[2]  = ab00 * cd10; s[3]  = ab00 * cd11;
        s[4]  = ab01 * cd00; s[5]  = ab01 * cd01; s[6]  = ab01 * cd10; s[7]  = ab01 * cd11;
        s[8]  = ab10 * cd00; s[9]  = ab10 * cd01; s[10] = ab10 * cd10; s[11] = ab10 * cd11;
        s[12] = ab11 * cd00; s[13] = ab11 * cd01; s[14] = ab11 * cd10; s[15] = ab11 * cd11;

        // split to bf16 hi (truncate) + lo (round) and stage row = lane
        uint32_t hp[8], lp[8];
#pragma unroll
        for (int p = 0; p < 8; p++) {
            float f0 = s[2 * p], f1 = s[2 * p + 1];
            hp[p] = pk_hi(f0, f1);
            lp[p] = pk_rn(f0 - hi_f32(f0), f1 - hi_f32(f1));
        }
        hrow[0] = make_uint4(hp[0], hp[1], hp[2], hp[3]);
        hrow[1] = make_uint4(hp[4], hp[5], hp[6], hp[7]);
        lrow[0] = make_uint4(lp[0], lp[1], lp[2], lp[3]);
        lrow[1] = make_uint4(lp[4], lp[5], lp[6], lp[7]);
        __syncwarp();

#pragma unroll
        for (int mt = 0; mt < 2; mt++) {
            uint32_t ah0, ah1, ah2, ah3, al0, al1, al2, al3;
            ldsm4(ah0, ah1, ah2, ah3, hibase + mt * (16 * ROWB) + lmoff);
            ldsm4(al0, al1, al2, al3, lobase + mt * (16 * ROWB) + lmoff);
#pragma unroll
            for (int nt = 0; nt < 2; nt++) {
                float d0 = 0.f, d1 = 0.f, d2 = 0.f, d3 = 0.f;
                mma16816(d0, d1, d2, d3, ah0, ah1, ah2, ah3, bh0[nt], bh1[nt]);
                mma16816(d0, d1, d2, d3, al0, al1, al2, al3, bh0[nt], bh1[nt]);
                mma16816(d0, d1, d2, d3, ah0, ah1, ah2, ah3, bl0[nt], bl1[nt]);
                mma16816(d0, d1, d2, d3, al0, al1, al2, al3, bl0[nt], bl1[nt]);
                P[mt][nt][0] = fmaf(d0, d0, P[mt][nt][0]);
                P[mt][nt][1] = fmaf(d1, d1, P[mt][nt][1]);
                P[mt][nt][2] = fmaf(d2, d2, P[mt][nt][2]);
                P[mt][nt][3] = fmaf(d3, d3, P[mt][nt][3]);
            }
        }
    }

    // ---- epilogue: per-lane signed combos, 4-lane bfly reduce, store ----
    // lane's columns: {2t, 2t+1} (nt0), {2t+8, 2t+9} (nt1)
    float s1 = ((2 * t) & 4) ? -1.0f : 1.0f;   // bit2 sign (same for all 4 cols)
    float s2 = ((2 * t) & 2) ? -1.0f : 1.0f;   // bit1 sign

    float zq[4][4];   // [mslot][q]
#pragma unroll
    for (int mt = 0; mt < 2; mt++) {
#pragma unroll
        for (int rs = 0; rs < 2; rs++) {   // rs=0: row g, rs=1: row g+8
            float Pa = P[mt][0][rs * 2 + 0];   // col 2t
            float Pb = P[mt][0][rs * 2 + 1];   // col 2t+1
            float Pc = P[mt][1][rs * 2 + 0];   // col 2t+8
            float Pd = P[mt][1][rs * 2 + 1];   // col 2t+9
            float ta = Pa + Pb, tb = Pc + Pd;
            float T  = ta + tb;
            int ms = mt * 2 + rs;
            zq[ms][0] = ta - tb;                       // bit3: cols<8 plus, >=8 minus
            zq[ms][1] = s1 * T;                        // bit2
            zq[ms][2] = s2 * T;                        // bit1
            zq[ms][3] = (Pa - Pb) + (Pc - Pd);         // bit0
        }
    }
#pragma unroll
    for (int ms = 0; ms < 4; ms++)
#pragma unroll
        for (int q = 0; q < 4; q++) {
            float v = zq[ms][q];
            v += __shfl_xor_sync(0xffffffffu, v, 1);
            v += __shfl_xor_sync(0xffffffffu, v, 2);
            zq[ms][q] = v;
        }

    if (t == 0) {
        int base = blockIdx.x * TPB + wid * 32;
#pragma unroll
        for (int ms = 0; ms < 4; ms++) {
            int pg = base + g + 8 * ms;   // ms: patches g, g+8, g+16, g+24
            if (pg < NLOC)
                reinterpret_cast<float4*>(out)[pg] =
                    make_float4(zq[ms][0], zq[ms][1], zq[ms][2], zq[ms][3]);
        }
    }
}

extern "C" void kernel_launch(void* const* d_in, const int* in_sizes, int n_in,
                              void* d_out, int out_size) {
    const float* x = (const float*)d_in[0];   // [32,3,128,128] float32
    const float* w = (const float*)d_in[1];   // [4,4] float32
    float* out = (float*)d_out;               // [32,4,127,127] float32

    int blocks = (NLOC + TPB - 1) / TPB;
    rqcnn_mma<<<blocks, TPB>>>(x, w, out);
}

// round 15
// speedup vs baseline: 1.6009x; 1.1131x over previous
#include <cuda_runtime.h>
#include <cstdint>

#define NB   32
#define NCH  3
#define HH   128
#define RR   127
#define NLOC (NB*RR*RR)
#define TPB  128
#define ROWB 48            // staging row pitch (conflict-free: 3r mod 8 distinct)

struct SmemT {
    float U[256];                                   // circuit matrix, f32
    __align__(16) unsigned char stage[4][2][32 * ROWB];  // [warp][hi/lo][row]
};

__device__ __forceinline__ uint32_t smem_u32(const void* p) {
    uint32_t a;
    asm("{ .reg .u64 t; cvta.to.shared.u64 t, %1; cvt.u32.u64 %0, t; }" : "=r"(a) : "l"(p));
    return a;
}
// bf16x2 truncation-pack via single PRMT: low half = hi16(a), high = hi16(b)
__device__ __forceinline__ uint32_t pk_hi(float a, float b) {
    uint32_t d;
    asm("prmt.b32 %0, %1, %2, 0x7632;" : "=r"(d) : "r"(__float_as_uint(a)), "r"(__float_as_uint(b)));
    return d;
}
__device__ __forceinline__ float hi_f32(float a) {
    return __uint_as_float(__float_as_uint(a) & 0xFFFF0000u);
}
__device__ __forceinline__ void ldsm4(uint32_t& r0, uint32_t& r1, uint32_t& r2, uint32_t& r3,
                                      uint32_t addr) {
    asm volatile("ldmatrix.sync.aligned.m8n8.x4.shared.b16 {%0,%1,%2,%3}, [%4];"
                 : "=r"(r0), "=r"(r1), "=r"(r2), "=r"(r3) : "r"(addr));
}
__device__ __forceinline__ void mma16816(float& d0, float& d1, float& d2, float& d3,
                                         uint32_t a0, uint32_t a1, uint32_t a2, uint32_t a3,
                                         uint32_t b0, uint32_t b1) {
    asm volatile("mma.sync.aligned.m16n8k16.row.col.f32.bf16.bf16.f32 "
                 "{%0,%1,%2,%3}, {%4,%5,%6,%7}, {%8,%9}, {%0,%1,%2,%3};"
                 : "+f"(d0), "+f"(d1), "+f"(d2), "+f"(d3)
                 : "r"(a0), "r"(a1), "r"(a2), "r"(a3), "r"(b0), "r"(b1));
}

__global__ void rqcnn_mma(const float* __restrict__ x,
                          const float* __restrict__ w,
                          float* __restrict__ out) {
    __shared__ SmemT sm;
    int tid  = threadIdx.x;
    int wid  = tid >> 5;
    int lane = tid & 31;

    // ---- build U (threads 0-15, column each) ----
    if (tid < 16) {
        int jj = tid;
        float m[16];
#pragma unroll
        for (int i = 0; i < 16; i++) m[i] = (i == jj) ? 1.0f : 0.0f;
        for (int layer = 0; layer < 4; layer++) {
#pragma unroll
            for (int q = 0; q < 4; q++) {
                float t = 0.5f * w[layer * 4 + q];
                float c, s;
                __sincosf(t, &s, &c);
                int mask = 8 >> q;
#pragma unroll
                for (int i0 = 0; i0 < 16; i0++) {
                    if (i0 & mask) continue;
                    int i1 = i0 | mask;
                    float a0 = m[i0], a1 = m[i1];
                    m[i0] = c * a0 - s * a1;
                    m[i1] = s * a0 + c * a1;
                }
            }
#pragma unroll
            for (int i = 0; i < 16; i++)
                if ((i & 8) && !(i & 4)) { float tt = m[i]; m[i] = m[i | 4]; m[i | 4] = tt; }
#pragma unroll
            for (int i = 0; i < 16; i++)
                if ((i & 2) && !(i & 1)) { float tt = m[i]; m[i] = m[i | 1]; m[i | 1] = tt; }
#pragma unroll
            for (int i = 0; i < 16; i++)
                if ((i & 4) && !(i & 2)) { float tt = m[i]; m[i] = m[i | 2]; m[i | 2] = tt; }
        }
#pragma unroll
        for (int i = 0; i < 16; i++) sm.U[i * 16 + jj] = m[i];
    }
    __syncthreads();

    int t = lane & 3, g = lane >> 2;

    // ---- B fragments (built once): B[k][n] = U[n][k], n = g + 8*nt ----
    uint32_t bh0[2], bh1[2], bl0[2], bl1[2];
#pragma unroll
    for (int nt = 0; nt < 2; nt++) {
        const float* Ur = sm.U + (g + 8 * nt) * 16;
        float u0 = Ur[2 * t],     u1 = Ur[2 * t + 1];
        float u2 = Ur[2 * t + 8], u3 = Ur[2 * t + 9];
        bh0[nt] = pk_hi(u0, u1);
        bh1[nt] = pk_hi(u2, u3);
        bl0[nt] = pk_hi(u0 - hi_f32(u0), u1 - hi_f32(u1));
        bl1[nt] = pk_hi(u2 - hi_f32(u2), u3 - hi_f32(u3));
    }

    // ---- per-lane patch ----
    int gid = blockIdx.x * TPB + tid;
    int gcl = (gid < NLOC) ? gid : (NLOC - 1);
    int j   = gcl % RR;
    int t2  = gcl / RR;
    int i   = t2 % RR;
    int b   = t2 / RR;
    const float HPI = 1.57079632679489662f;

    uint32_t hibase = smem_u32(&sm.stage[wid][0][0]);
    uint32_t lobase = smem_u32(&sm.stage[wid][1][0]);
    uint4* hrow = reinterpret_cast<uint4*>(&sm.stage[wid][0][lane * ROWB]);
    uint4* lrow = reinterpret_cast<uint4*>(&sm.stage[wid][1][lane * ROWB]);
    uint32_t lmoff = (uint32_t)((lane & 15) * ROWB + (lane & 16));

    float P[2][2][4];
#pragma unroll
    for (int a = 0; a < 2; a++)
#pragma unroll
        for (int n = 0; n < 2; n++)
#pragma unroll
            for (int e = 0; e < 4; e++) P[a][n][e] = 0.0f;

    const float* px = x + (((b * NCH) * HH) + i) * HH + j;

    // prefetch channel 0 pixels
    float q00 = px[0], q01 = px[1], q10 = px[HH], q11 = px[HH + 1];
    px += HH * HH;

#pragma unroll 1
    for (int c = 0; c < NCH; c++) {
        float p00 = q00, p01 = q01, p10 = q10, p11 = q11;
        if (c < NCH - 1) {       // prefetch next channel before compute/MMA
            q00 = px[0]; q01 = px[1]; q10 = px[HH]; q11 = px[HH + 1];
            px += HH * HH;
        }

        __syncwarp();   // prior ldmatrix done before staging overwrite

        float ca, sa, cb, sb, cc, sc, cd, sd;
        __sincosf(p00 * HPI, &sa, &ca);
        __sincosf(p01 * HPI, &sb, &cb);
        __sincosf(p10 * HPI, &sc, &cc);
        __sincosf(p11 * HPI, &sd, &cd);
        float ab00 = ca * cb, ab01 = ca * sb, ab10 = sa * cb, ab11 = sa * sb;
        float cd00 = cc * cd, cd01 = cc * sd, cd10 = sc * cd, cd11 = sc * sd;
        float s[16];
        s[0]  = ab00 * cd00; s[1]  = ab00 * cd01; s[2]  = ab00 * cd10; s[3]  = ab00 * cd11;
        s[4]  = ab01 * cd00; s[5]  = ab01 * cd01; s[6]  = ab01 * cd10; s[7]  = ab01 * cd11;
        s[8]  = ab10 * cd00; s[9]  = ab10 * cd01; s[10] = ab10 * cd10; s[11] = ab10 * cd11;
        s[12] = ab11 * cd00; s[13] = ab11 * cd01; s[14] = ab11 * cd10; s[15] = ab11 * cd11;

        // split to bf16 hi + lo (both truncation-packed via PRMT), stage row=lane
        uint32_t hp[8], lp[8];
#pragma unroll
        for (int p = 0; p < 8; p++) {
            float f0 = s[2 * p], f1 = s[2 * p + 1];
            hp[p] = pk_hi(f0, f1);
            lp[p] = pk_hi(f0 - hi_f32(f0), f1 - hi_f32(f1));
        }
        hrow[0] = make_uint4(hp[0], hp[1], hp[2], hp[3]);
        hrow[1] = make_uint4(hp[4], hp[5], hp[6], hp[7]);
        lrow[0] = make_uint4(lp[0], lp[1], lp[2], lp[3]);
        lrow[1] = make_uint4(lp[4], lp[5], lp[6], lp[7]);
        __syncwarp();

#pragma unroll
        for (int mt = 0; mt < 2; mt++) {
            uint32_t ah0, ah1, ah2, ah3, al0, al1, al2, al3;
            ldsm4(ah0, ah1, ah2, ah3, hibase + mt * (16 * ROWB) + lmoff);
            ldsm4(al0, al1, al2, al3, lobase + mt * (16 * ROWB) + lmoff);
#pragma unroll
            for (int nt = 0; nt < 2; nt++) {
                float d0 = 0.f, d1 = 0.f, d2 = 0.f, d3 = 0.f;
                mma16816(d0, d1, d2, d3, ah0, ah1, ah2, ah3, bh0[nt], bh1[nt]);
                mma16816(d0, d1, d2, d3, al0, al1, al2, al3, bh0[nt], bh1[nt]);
                mma16816(d0, d1, d2, d3, ah0, ah1, ah2, ah3, bl0[nt], bl1[nt]);
                // lo x lo term dropped: ~2^-34 relative, numerically invisible
                P[mt][nt][0] = fmaf(d0, d0, P[mt][nt][0]);
                P[mt][nt][1] = fmaf(d1, d1, P[mt][nt][1]);
                P[mt][nt][2] = fmaf(d2, d2, P[mt][nt][2]);
                P[mt][nt][3] = fmaf(d3, d3, P[mt][nt][3]);
            }
        }
    }

    // ---- epilogue: per-lane signed combos, 4-lane bfly reduce, store ----
    float s1 = ((2 * t) & 4) ? -1.0f : 1.0f;   // bit2 sign
    float s2 = ((2 * t) & 2) ? -1.0f : 1.0f;   // bit1 sign

    float zq[4][4];   // [mslot][q]
#pragma unroll
    for (int mt = 0; mt < 2; mt++) {
#pragma unroll
        for (int rs = 0; rs < 2; rs++) {
            float Pa = P[mt][0][rs * 2 + 0];
            float Pb = P[mt][0][rs * 2 + 1];
            float Pc = P[mt][1][rs * 2 + 0];
            float Pd = P[mt][1][rs * 2 + 1];
            float ta = Pa + Pb, tb = Pc + Pd;
            float T  = ta + tb;
            int ms = mt * 2 + rs;
            zq[ms][0] = ta - tb;
            zq[ms][1] = s1 * T;
            zq[ms][2] = s2 * T;
            zq[ms][3] = (Pa - Pb) + (Pc - Pd);
        }
    }
#pragma unroll
    for (int ms = 0; ms < 4; ms++)
#pragma unroll
        for (int q = 0; q < 4; q++) {
            float v = zq[ms][q];
            v += __shfl_xor_sync(0xffffffffu, v, 1);
            v += __shfl_xor_sync(0xffffffffu, v, 2);
            zq[ms][q] = v;
        }

    if (t == 0) {
        int base = blockIdx.x * TPB + wid * 32;
#pragma unroll
        for (int ms = 0; ms < 4; ms++) {
            int pg = base + g + 8 * ms;
            if (pg < NLOC)
                reinterpret_cast<float4*>(out)[pg] =
                    make_float4(zq[ms][0], zq[ms][1], zq[ms][2], zq[ms][3]);
        }
    }
}

extern "C" void kernel_launch(void* const* d_in, const int* in_sizes, int n_in,
                              void* d_out, int out_size) {
    const float* x = (const float*)d_in[0];   // [32,3,128,128] float32
    const float* w = (const float*)d_in[1];   // [4,4] float32
    float* out = (float*)d_out;               // [32,4,127,127] float32

    int blocks = (NLOC + TPB - 1) / TPB;
    rqcnn_mma<<<blocks, TPB>>>(x, w, out);
}